// round 2
// baseline (speedup 1.0000x reference)
#include <cuda_runtime.h>
#include <math.h>

// Problem constants
#define BB   2
#define LL   8192
#define DD   1024
#define HH   8
#define DH   128
#define NROW (BB*LL)     // 16384
#define DFF  (2*DD)      // 2048
#define LC   512
#define NCH  (LL/LC)     // 16
#define ATTN_EPS 1e-6f
#define LN_EPS   1e-5f

// Scratch (device globals: allocation-free per harness rules)
__device__ float g_q[NROW*DD];                 // x @ Wq
__device__ float g_msg[NROW*DD];               // attention message (pre-Wm)
__device__ float g_tmp[NROW*DD];               // msg@Wm, then reused for mlp out
__device__ float g_h1[NROW*DFF];               // relu((msg@Wm)@W1)
__device__ float g_kvp[BB*HH*NCH*DH*DH];       // KV partials per L-chunk
__device__ float g_kv[BB*HH*DH*DH];            // KV
__device__ float g_ksp[BB*HH*NCH*DH];          // Ksum partials
__device__ float g_ks[BB*HH*DH];               // Ksum
__device__ float g_z[NROW*HH];                 // 1/(Q.Ksum + eps)

__device__ __forceinline__ float featf(float v) {
    // elu(v)+1:  v>0 -> v+1 ; else exp(v)
    return v > 0.f ? v + 1.f : expf(v);
}

// ---------------------------------------------------------------------------
// Tiled SGEMM: C[M,N] = A[M,K] @ B[K,N], row-major, M%128==0, N%128==0, K%16==0
// EPI: 0 = plain store, 1 = relu
// ---------------------------------------------------------------------------
#define BM 128
#define BN 128
#define BK 16
#define TM 8
#define TN 8

template <int EPI>
__global__ void __launch_bounds__(256) sgemm_k(const float* __restrict__ A,
                                               const float* __restrict__ B,
                                               float* __restrict__ C,
                                               int M, int N, int K) {
    __shared__ __align__(16) float As[BK][BM];
    __shared__ __align__(16) float Bs[BK][BN];
    const int tid = threadIdx.x;
    const int brow = blockIdx.y, bcol = blockIdx.x;
    const float* Ab = A + (size_t)brow * BM * K;
    const float* Bbp = B + (size_t)bcol * BN;

    const int rowA = tid >> 2;           // 0..63
    const int colA = (tid & 3) * 4;      // 0,4,8,12
    const int rowB = tid >> 5;           // 0..7
    const int colB = (tid & 31) * 4;     // 0..124
    const int tr = (tid >> 4) * TM;
    const int tc = (tid & 15) * TN;

    float acc[TM][TN] = {};

    for (int k0 = 0; k0 < K; k0 += BK) {
#pragma unroll
        for (int i = 0; i < 2; i++) {
            float4 v = *(const float4*)(Ab + (size_t)(rowA + i * 64) * K + k0 + colA);
            As[colA + 0][rowA + i * 64] = v.x;
            As[colA + 1][rowA + i * 64] = v.y;
            As[colA + 2][rowA + i * 64] = v.z;
            As[colA + 3][rowA + i * 64] = v.w;
        }
#pragma unroll
        for (int i = 0; i < 2; i++) {
            float4 v = *(const float4*)(Bbp + (size_t)(k0 + rowB + i * 8) * N + colB);
            *(float4*)(&Bs[rowB + i * 8][colB]) = v;
        }
        __syncthreads();
#pragma unroll
        for (int kk = 0; kk < BK; kk++) {
            float4 a0 = *(const float4*)&As[kk][tr];
            float4 a1 = *(const float4*)&As[kk][tr + 4];
            float4 b0 = *(const float4*)&Bs[kk][tc];
            float4 b1 = *(const float4*)&Bs[kk][tc + 4];
            float ra[TM] = {a0.x, a0.y, a0.z, a0.w, a1.x, a1.y, a1.z, a1.w};
            float rb[TN] = {b0.x, b0.y, b0.z, b0.w, b1.x, b1.y, b1.z, b1.w};
#pragma unroll
            for (int i = 0; i < TM; i++)
#pragma unroll
                for (int j = 0; j < TN; j++)
                    acc[i][j] = fmaf(ra[i], rb[j], acc[i][j]);
        }
        __syncthreads();
    }
#pragma unroll
    for (int i = 0; i < TM; i++) {
        float* Crow = C + (size_t)(brow * BM + tr + i) * N + bcol * BN + tc;
#pragma unroll
        for (int j = 0; j < TN; j += 4) {
            float4 v;
            v.x = acc[i][j]; v.y = acc[i][j + 1]; v.z = acc[i][j + 2]; v.w = acc[i][j + 3];
            if (EPI == 1) {
                v.x = fmaxf(v.x, 0.f); v.y = fmaxf(v.y, 0.f);
                v.z = fmaxf(v.z, 0.f); v.w = fmaxf(v.w, 0.f);
            }
            *(float4*)(Crow + j) = v;
        }
    }
}

// ---------------------------------------------------------------------------
// KV partials: for (b,h,chunk c): KVp = sum_{l in chunk} feat(q)[l,:]^T (q/L)[l,:]
// grid (NCH, B*H), 256 threads. Output 128x128 per block.
// ---------------------------------------------------------------------------
__global__ void __launch_bounds__(256) kv_part_k() {
    const int ch = blockIdx.x, bh = blockIdx.y;
    const int b = bh >> 3, h = bh & 7;
    __shared__ __align__(16) float Fs[BK][DH];
    __shared__ __align__(16) float Vs[BK][DH];
    const float invL = 1.0f / (float)LL;
    const int tid = threadIdx.x;
    const int rowL = tid >> 5;           // 0..7
    const int colL = (tid & 31) * 4;
    const int tr = (tid >> 4) * 8, tc = (tid & 15) * 8;
    float acc[8][8] = {};

    for (int l0 = ch * LC; l0 < ch * LC + LC; l0 += BK) {
#pragma unroll
        for (int i = 0; i < 2; i++) {
            int l = l0 + rowL + i * 8;
            const float* p = g_q + (size_t)(b * LL + l) * DD + h * DH + colL;
            float4 v = *(const float4*)p;
            float4 f;
            f.x = featf(v.x); f.y = featf(v.y); f.z = featf(v.z); f.w = featf(v.w);
            *(float4*)&Fs[rowL + i * 8][colL] = f;
            float4 vv; vv.x = v.x * invL; vv.y = v.y * invL; vv.z = v.z * invL; vv.w = v.w * invL;
            *(float4*)&Vs[rowL + i * 8][colL] = vv;
        }
        __syncthreads();
#pragma unroll
        for (int kk = 0; kk < BK; kk++) {
            float4 a0 = *(const float4*)&Fs[kk][tr];
            float4 a1 = *(const float4*)&Fs[kk][tr + 4];
            float4 b0 = *(const float4*)&Vs[kk][tc];
            float4 b1 = *(const float4*)&Vs[kk][tc + 4];
            float ra[8] = {a0.x, a0.y, a0.z, a0.w, a1.x, a1.y, a1.z, a1.w};
            float rb[8] = {b0.x, b0.y, b0.z, b0.w, b1.x, b1.y, b1.z, b1.w};
#pragma unroll
            for (int i = 0; i < 8; i++)
#pragma unroll
                for (int j = 0; j < 8; j++)
                    acc[i][j] = fmaf(ra[i], rb[j], acc[i][j]);
        }
        __syncthreads();
    }
    float* outp = g_kvp + (size_t)(bh * NCH + ch) * (DH * DH);
#pragma unroll
    for (int i = 0; i < 8; i++)
#pragma unroll
        for (int j = 0; j < 8; j += 4) {
            float4 v;
            v.x = acc[i][j]; v.y = acc[i][j + 1]; v.z = acc[i][j + 2]; v.w = acc[i][j + 3];
            *(float4*)(outp + (tr + i) * DH + tc + j) = v;
        }
}

__global__ void kv_reduce_k() {
    int idx = blockIdx.x * 256 + threadIdx.x;          // B*H*16384 total
    int bh = idx >> 14;
    int e = idx & 16383;
    float s = 0.f;
#pragma unroll
    for (int c = 0; c < NCH; c++)
        s += g_kvp[(size_t)(bh * NCH + c) * (DH * DH) + e];
    g_kv[idx] = s;
}

// Ksum partials: grid (NCH, B*H), 128 threads
__global__ void __launch_bounds__(128) ksum_part_k() {
    const int ch = blockIdx.x, bh = blockIdx.y;
    const int b = bh >> 3, h = bh & 7;
    const int i = threadIdx.x;
    float s = 0.f;
    const float* base = g_q + (size_t)(b * LL + ch * LC) * DD + h * DH + i;
    for (int l = 0; l < LC; l++)
        s += featf(base[(size_t)l * DD]);
    g_ksp[(bh * NCH + ch) * DH + i] = s;
}

__global__ void ksum_reduce_k() {
    int idx = blockIdx.x * 256 + threadIdx.x;          // B*H*128 = 2048
    int bh = idx >> 7;
    int i = idx & 127;
    float s = 0.f;
#pragma unroll
    for (int c = 0; c < NCH; c++)
        s += g_ksp[(bh * NCH + c) * DH + i];
    g_ks[idx] = s;
}

// Z = 1/(dot(feat(q)[n,h,:], Ksum[b,h,:]) + eps); grid 512 x 256 threads
__global__ void __launch_bounds__(256) z_k() {
    __shared__ float sk[BB * HH * DH];   // 2048 floats
    for (int i = threadIdx.x; i < BB * HH * DH; i += 256) sk[i] = g_ks[i];
    __syncthreads();
    int idx = blockIdx.x * 256 + threadIdx.x;          // n*H + h, total 131072
    int n = idx >> 3;
    int h = idx & 7;
    int b = n >> 13;
    const float* qp = g_q + (size_t)n * DD + h * DH;
    const float* kp = sk + (b * HH + h) * DH;
    float dot = 0.f;
#pragma unroll 4
    for (int i = 0; i < DH; i += 4) {
        float4 v = *(const float4*)(qp + i);
        dot = fmaf(featf(v.x), kp[i + 0], dot);
        dot = fmaf(featf(v.y), kp[i + 1], dot);
        dot = fmaf(featf(v.z), kp[i + 2], dot);
        dot = fmaf(featf(v.w), kp[i + 3], dot);
    }
    g_z[idx] = 1.0f / (dot + ATTN_EPS);
}

// msg[n, h*128+j] = (sum_d feat(q)[n,h,d] * KV[b,h,d,j]) * Z[n,h] * L
// grid (L/128, B*H), 256 threads
__global__ void __launch_bounds__(256) msg_k() {
    const int bh = blockIdx.y;
    const int b = bh >> 3, h = bh & 7;
    const int l0 = blockIdx.x * BM;
    __shared__ __align__(16) float As[BK][BM];
    __shared__ __align__(16) float Ks[BK][DH];
    const int tid = threadIdx.x;
    const int rowA = tid >> 2;
    const int colA = (tid & 3) * 4;
    const int rowB = tid >> 5;
    const int colB = (tid & 31) * 4;
    const int tr = (tid >> 4) * 8, tc = (tid & 15) * 8;
    float acc[8][8] = {};
    const float* kvb = g_kv + (size_t)bh * (DH * DH);

    for (int k0 = 0; k0 < DH; k0 += BK) {
#pragma unroll
        for (int i = 0; i < 2; i++) {
            int l = l0 + rowA + i * 64;
            float4 v = *(const float4*)(g_q + (size_t)(b * LL + l) * DD + h * DH + k0 + colA);
            As[colA + 0][rowA + i * 64] = featf(v.x);
            As[colA + 1][rowA + i * 64] = featf(v.y);
            As[colA + 2][rowA + i * 64] = featf(v.z);
            As[colA + 3][rowA + i * 64] = featf(v.w);
        }
#pragma unroll
        for (int i = 0; i < 2; i++) {
            float4 v = *(const float4*)(kvb + (size_t)(k0 + rowB + i * 8) * DH + colB);
            *(float4*)(&Ks[rowB + i * 8][colB]) = v;
        }
        __syncthreads();
#pragma unroll
        for (int kk = 0; kk < BK; kk++) {
            float4 a0 = *(const float4*)&As[kk][tr];
            float4 a1 = *(const float4*)&As[kk][tr + 4];
            float4 b0 = *(const float4*)&Ks[kk][tc];
            float4 b1 = *(const float4*)&Ks[kk][tc + 4];
            float ra[8] = {a0.x, a0.y, a0.z, a0.w, a1.x, a1.y, a1.z, a1.w};
            float rb[8] = {b0.x, b0.y, b0.z, b0.w, b1.x, b1.y, b1.z, b1.w};
#pragma unroll
            for (int i = 0; i < 8; i++)
#pragma unroll
                for (int j = 0; j < 8; j++)
                    acc[i][j] = fmaf(ra[i], rb[j], acc[i][j]);
        }
        __syncthreads();
    }
#pragma unroll
    for (int i = 0; i < 8; i++) {
        int n = b * LL + l0 + tr + i;
        float zs = g_z[n * HH + h] * (float)LL;
        float* op = g_msg + (size_t)n * DD + h * DH + tc;
#pragma unroll
        for (int j = 0; j < 8; j += 4) {
            float4 v;
            v.x = acc[i][j] * zs; v.y = acc[i][j + 1] * zs;
            v.z = acc[i][j + 2] * zs; v.w = acc[i][j + 3] * zs;
            *(float4*)(op + j) = v;
        }
    }
}

// ---------------------------------------------------------------------------
// LayerNorm + residual: out[n,:] = base[n,:] + LN(t[n,:])*g + bias
// ---------------------------------------------------------------------------
__device__ __forceinline__ float warpReduceSum(float v) {
#pragma unroll
    for (int o = 16; o > 0; o >>= 1) v += __shfl_xor_sync(0xffffffffu, v, o);
    return v;
}

__global__ void __launch_bounds__(256) ln_k(const float* __restrict__ t,
                                            const float* __restrict__ base,
                                            const float* __restrict__ gam,
                                            const float* __restrict__ bet,
                                            float* __restrict__ out) {
    const int n = blockIdx.x;
    __shared__ float row[DD];
    __shared__ float rs[8], rs2[8];
    __shared__ float smu, srstd;
    const float* tp = t + (size_t)n * DD;
    float s = 0.f, s2 = 0.f;
    for (int d = threadIdx.x; d < DD; d += 256) {
        float v = tp[d];
        row[d] = v;
        s += v;
        s2 = fmaf(v, v, s2);
    }
    s = warpReduceSum(s);
    s2 = warpReduceSum(s2);
    int lane = threadIdx.x & 31, wid = threadIdx.x >> 5;
    if (lane == 0) { rs[wid] = s; rs2[wid] = s2; }
    __syncthreads();
    if (threadIdx.x < 32) {
        float a = (threadIdx.x < 8) ? rs[threadIdx.x] : 0.f;
        float b2 = (threadIdx.x < 8) ? rs2[threadIdx.x] : 0.f;
        a = warpReduceSum(a);
        b2 = warpReduceSum(b2);
        if (threadIdx.x == 0) {
            float mu = a * (1.0f / DD);
            float var = b2 * (1.0f / DD) - mu * mu;
            smu = mu;
            srstd = rsqrtf(var + LN_EPS);
        }
    }
    __syncthreads();
    float mu = smu, rstd = srstd;
    const float* bp = base + (size_t)n * DD;
    float* op = out + (size_t)n * DD;
    for (int d = threadIdx.x; d < DD; d += 256)
        op[d] = bp[d] + (row[d] - mu) * rstd * gam[d] + bet[d];
}

// ---------------------------------------------------------------------------
extern "C" void kernel_launch(void* const* d_in, const int* in_sizes, int n_in,
                              void* d_out, int out_size) {
    (void)in_sizes; (void)n_in; (void)out_size;
    const float* x  = (const float*)d_in[0];
    const float* Wq = (const float*)d_in[1];
    const float* Wm = (const float*)d_in[2];
    const float* W1 = (const float*)d_in[3];
    const float* W2 = (const float*)d_in[4];
    const float* g1 = (const float*)d_in[5];
    const float* b1 = (const float*)d_in[6];
    const float* g2 = (const float*)d_in[7];
    const float* b2 = (const float*)d_in[8];
    float* out = (float*)d_out;

    float *q, *msg, *tmp, *h1;
    cudaGetSymbolAddress((void**)&q,   g_q);
    cudaGetSymbolAddress((void**)&msg, g_msg);
    cudaGetSymbolAddress((void**)&tmp, g_tmp);
    cudaGetSymbolAddress((void**)&h1,  g_h1);

    // 1. q = x @ Wq
    sgemm_k<0><<<dim3(DD / BN, NROW / BM), 256>>>(x, Wq, q, NROW, DD, DD);
    // 2-3. KV = sum_l feat^T (q/L)
    kv_part_k<<<dim3(NCH, BB * HH), 256>>>();
    kv_reduce_k<<<BB * HH * DH * DH / 256, 256>>>();
    // 4. Ksum
    ksum_part_k<<<dim3(NCH, BB * HH), 128>>>();
    ksum_reduce_k<<<BB * HH * DH / 256, 256>>>();
    // 5. Z
    z_k<<<NROW * HH / 256, 256>>>();
    // 6. msg (pre-merge attention output)
    msg_k<<<dim3(LL / BM, BB * HH), 256>>>();
    // 7. merged = msg @ Wm -> tmp   (this is the "msg" the reference rebinds!)
    sgemm_k<0><<<dim3(DD / BN, NROW / BM), 256>>>(msg, Wm, tmp, NROW, DD, DD);
    // 8. out = x + LN(tmp)
    ln_k<<<NROW, 256>>>(tmp, x, g1, b1, out);
    // 9. h1 = relu(tmp @ W1)   [MLP input is the POST-Wm message]
    sgemm_k<1><<<dim3(DFF / BN, NROW / BM), 256>>>(tmp, W1, h1, NROW, DFF, DD);
    // 10. tmp = h1 @ W2
    sgemm_k<0><<<dim3(DD / BN, NROW / BM), 256>>>(h1, W2, tmp, NROW, DD, DFF);
    // 11. out += LN(tmp)
    ln_k<<<NROW, 256>>>(tmp, out, g2, b2, out);
}

// round 4
// speedup vs baseline: 3.7070x; 3.7070x over previous
#include <cuda_runtime.h>
#include <cuda_bf16.h>
#include <math.h>
#include <stdint.h>

// Problem constants
#define BB   2
#define LL   8192
#define DD   1024
#define HH   8
#define DH   128
#define NROW (BB*LL)     // 16384
#define DFF  (2*DD)      // 2048
#define LC   512
#define NCH  (LL/LC)     // 16
#define ATTN_EPS 1e-6f
#define LN_EPS   1e-5f

// ---------------------------------------------------------------------------
// Scratch (device globals: allocation-free per harness rules)
// ---------------------------------------------------------------------------
__device__ float g_q[NROW*DD];                  // x @ Wq (fp32, attention input)
__device__ float g_tmp[NROW*DD];                // msg@Wm fp32 (LN1 input), then mlp out
__device__ float g_kvp[BB*HH*NCH*DH*DH];        // KV partials per L-chunk
__device__ float g_kv[BB*HH*DH*DH];             // KV
__device__ float g_ksp[BB*HH*NCH*DH];           // Ksum partials
__device__ float g_ks[BB*HH*DH];                // Ksum
__device__ float g_z[NROW*HH];                  // 1/(Q.Ksum + eps)

// bf16 hi/lo split operands for tensor-core GEMMs
__device__ __nv_bfloat16 g_x_hi[NROW*DD],   g_x_lo[NROW*DD];
__device__ __nv_bfloat16 g_msg_hi[NROW*DD], g_msg_lo[NROW*DD];
__device__ __nv_bfloat16 g_tmp_hi[NROW*DD], g_tmp_lo[NROW*DD];
__device__ __nv_bfloat16 g_h1_hi[NROW*DFF], g_h1_lo[NROW*DFF];
// transposed+split weights: [N, K] K-major
__device__ __nv_bfloat16 g_wq_hi[DD*DD],  g_wq_lo[DD*DD];
__device__ __nv_bfloat16 g_wm_hi[DD*DD],  g_wm_lo[DD*DD];
__device__ __nv_bfloat16 g_w1_hi[DFF*DD], g_w1_lo[DFF*DD];
__device__ __nv_bfloat16 g_w2_hi[DD*DFF], g_w2_lo[DD*DFF];

// ---------------------------------------------------------------------------
// Helpers
// ---------------------------------------------------------------------------
__device__ __forceinline__ uint32_t smem_u32(const void* p) {
    uint32_t a;
    asm("{ .reg .u64 t; cvta.to.shared.u64 t, %1; cvt.u32.u64 %0, t; }" : "=r"(a) : "l"(p));
    return a;
}

__device__ __forceinline__ void splitf(float v, __nv_bfloat16& h, __nv_bfloat16& l) {
    h = __float2bfloat16(v);
    l = __float2bfloat16(v - __bfloat162float(h));
}

__device__ __forceinline__ float featf(float v) {
    return v > 0.f ? v + 1.f : expf(v);
}

#define LDSM4(r0, r1, r2, r3, addr) \
    asm volatile("ldmatrix.sync.aligned.m8n8.x4.shared.b16 {%0,%1,%2,%3}, [%4];" \
                 : "=r"(r0), "=r"(r1), "=r"(r2), "=r"(r3) : "r"(addr))

__device__ __forceinline__ void mma16816(float* c, const uint32_t* a,
                                         uint32_t b0, uint32_t b1) {
    asm volatile("mma.sync.aligned.m16n8k16.row.col.f32.bf16.bf16.f32 "
                 "{%0,%1,%2,%3}, {%4,%5,%6,%7}, {%8,%9}, {%0,%1,%2,%3};"
                 : "+f"(c[0]), "+f"(c[1]), "+f"(c[2]), "+f"(c[3])
                 : "r"(a[0]), "r"(a[1]), "r"(a[2]), "r"(a[3]), "r"(b0), "r"(b1));
}

// ---------------------------------------------------------------------------
// HMMA GEMM: C[M,N] = (Ahi+Alo)[M,K] @ (Bhi+Blo)^T, B stored [N,K] K-major.
// Block tile 128x128, K-chunk 32; 8 warps (2x4), warp tile 64x32.
// Hi/lo 3-pass: ah*bh + al*bh + ah*bl (lo*lo dropped).
// EPI: 0 = fp32 C; 1 = fp32 C + bf16 hi/lo; 2 = relu then bf16 hi/lo only.
// smem rows padded to 80B (40 bf16): conflict-free ldmatrix phases.
// ---------------------------------------------------------------------------
#define SROW 80

template <int EPI>
__global__ void __launch_bounds__(256, 2)
hgemm_k(const __nv_bfloat16* __restrict__ Ahi, const __nv_bfloat16* __restrict__ Alo,
        const __nv_bfloat16* __restrict__ Bhi, const __nv_bfloat16* __restrict__ Blo,
        float* __restrict__ C, __nv_bfloat16* __restrict__ Chi,
        __nv_bfloat16* __restrict__ Clo, int Nn, int K) {
    __shared__ __align__(16) char sAh[128 * SROW], sAl[128 * SROW];
    __shared__ __align__(16) char sBh[128 * SROW], sBl[128 * SROW];
    const int tid = threadIdx.x, warp = tid >> 5, lane = tid & 31;
    const int wm = warp >> 2, wn = warp & 3;           // 2 x 4 warp grid
    const int m0 = blockIdx.y * 128, n0 = blockIdx.x * 128;

    float acc[4][4][4] = {};   // [mtile][ntile][reg]

    const uint32_t sbAh = smem_u32(sAh), sbAl = smem_u32(sAl);
    const uint32_t sbBh = smem_u32(sBh), sbBl = smem_u32(sBl);
    // ldmatrix per-lane offsets
    const uint32_t aoff = (uint32_t)(wm * 64 + (lane & 15)) * SROW + ((lane >> 4) << 4);
    const int nloc = (lane & 7) + ((lane >> 4) << 3);
    const uint32_t boff = (uint32_t)(wn * 32 + nloc) * SROW + (((lane >> 3) & 1) << 4);

    const int ldrow = tid >> 2, ldu = tid & 3;
    const uint32_t ldso = (uint32_t)ldrow * SROW + ldu * 16;

    for (int kc = 0; kc < K; kc += 32) {
        __syncthreads();   // previous chunk's ldmatrix reads done
#pragma unroll
        for (int i = 0; i < 2; i++) {
            int row = ldrow + i * 64;
            uint32_t so = ldso + (uint32_t)i * 64 * SROW;
            const size_t ga = (size_t)(m0 + row) * K + kc;
            const size_t gb = (size_t)(n0 + row) * K + kc;
            *(uint4*)(sAh + so) = *((const uint4*)(Ahi + ga) + ldu);
            *(uint4*)(sAl + so) = *((const uint4*)(Alo + ga) + ldu);
            *(uint4*)(sBh + so) = *((const uint4*)(Bhi + gb) + ldu);
            *(uint4*)(sBl + so) = *((const uint4*)(Blo + gb) + ldu);
        }
        __syncthreads();
#pragma unroll
        for (int ks = 0; ks < 2; ks++) {
            const uint32_t kso = (uint32_t)ks * 32;    // 16 bf16 = 32 bytes
            uint32_t ah[4][4], al[4][4], b[2][4];
            // pass 1: ah * bh
#pragma unroll
            for (int mt = 0; mt < 4; mt++)
                LDSM4(ah[mt][0], ah[mt][1], ah[mt][2], ah[mt][3],
                      sbAh + aoff + (uint32_t)mt * 16 * SROW + kso);
#pragma unroll
            for (int p = 0; p < 2; p++)
                LDSM4(b[p][0], b[p][1], b[p][2], b[p][3],
                      sbBh + boff + (uint32_t)p * 16 * SROW + kso);
#pragma unroll
            for (int mt = 0; mt < 4; mt++)
#pragma unroll
                for (int p = 0; p < 2; p++) {
                    mma16816(acc[mt][p * 2 + 0], ah[mt], b[p][0], b[p][1]);
                    mma16816(acc[mt][p * 2 + 1], ah[mt], b[p][2], b[p][3]);
                }
            // pass 2: al * bh
#pragma unroll
            for (int mt = 0; mt < 4; mt++)
                LDSM4(al[mt][0], al[mt][1], al[mt][2], al[mt][3],
                      sbAl + aoff + (uint32_t)mt * 16 * SROW + kso);
#pragma unroll
            for (int mt = 0; mt < 4; mt++)
#pragma unroll
                for (int p = 0; p < 2; p++) {
                    mma16816(acc[mt][p * 2 + 0], al[mt], b[p][0], b[p][1]);
                    mma16816(acc[mt][p * 2 + 1], al[mt], b[p][2], b[p][3]);
                }
            // pass 3: ah * bl (reuse b regs)
#pragma unroll
            for (int p = 0; p < 2; p++)
                LDSM4(b[p][0], b[p][1], b[p][2], b[p][3],
                      sbBl + boff + (uint32_t)p * 16 * SROW + kso);
#pragma unroll
            for (int mt = 0; mt < 4; mt++)
#pragma unroll
                for (int p = 0; p < 2; p++) {
                    mma16816(acc[mt][p * 2 + 0], ah[mt], b[p][0], b[p][1]);
                    mma16816(acc[mt][p * 2 + 1], ah[mt], b[p][2], b[p][3]);
                }
        }
    }

    // Epilogue: acc reg mapping m16n8: c0,c1=(gid, t4*2,+1); c2,c3=(gid+8, ...)
    const int gid = lane >> 2, t4 = lane & 3;
#pragma unroll
    for (int mt = 0; mt < 4; mt++) {
#pragma unroll
        for (int nt = 0; nt < 4; nt++) {
            const float* c = acc[mt][nt];
            const int r0 = m0 + wm * 64 + mt * 16 + gid;
            const int cc = n0 + wn * 32 + nt * 8 + t4 * 2;
#pragma unroll
            for (int half = 0; half < 2; half++) {
                const int r = r0 + half * 8;
                float v0 = c[half * 2 + 0], v1 = c[half * 2 + 1];
                if (EPI <= 1) {
                    float2 f; f.x = v0; f.y = v1;
                    *(float2*)(C + (size_t)r * Nn + cc) = f;
                }
                if (EPI >= 1) {
                    if (EPI == 2) { v0 = fmaxf(v0, 0.f); v1 = fmaxf(v1, 0.f); }
                    __nv_bfloat16 h0, l0, h1, l1;
                    splitf(v0, h0, l0);
                    splitf(v1, h1, l1);
                    __nv_bfloat162 hh; hh.x = h0; hh.y = h1;
                    __nv_bfloat162 ll; ll.x = l0; ll.y = l1;
                    *(__nv_bfloat162*)(Chi + (size_t)r * Nn + cc) = hh;
                    *(__nv_bfloat162*)(Clo + (size_t)r * Nn + cc) = ll;
                }
            }
        }
    }
}

// ---------------------------------------------------------------------------
// Conversion kernels
// ---------------------------------------------------------------------------
__global__ void split_k(const float* __restrict__ in, __nv_bfloat16* __restrict__ hi,
                        __nv_bfloat16* __restrict__ lo, int n) {
    int i = blockIdx.x * 256 + threadIdx.x;
    if (i < n) {
        __nv_bfloat16 h, l;
        splitf(in[i], h, l);
        hi[i] = h;
        lo[i] = l;
    }
}

// W [K,N] fp32 -> Wt_hi/lo [N,K] bf16
__global__ void wtrans_k(const float* __restrict__ W, __nv_bfloat16* __restrict__ Thi,
                         __nv_bfloat16* __restrict__ Tlo, int K, int N) {
    int idx = blockIdx.x * 256 + threadIdx.x;
    if (idx < N * K) {
        int n = idx / K, k = idx - n * K;
        __nv_bfloat16 h, l;
        splitf(W[(size_t)k * N + n], h, l);
        Thi[idx] = h;
        Tlo[idx] = l;
    }
}

// ---------------------------------------------------------------------------
// Attention pieces (fp32 SIMT; small fraction of runtime)
// ---------------------------------------------------------------------------
#define BK16 16

__global__ void __launch_bounds__(256) kv_part_k() {
    const int ch = blockIdx.x, bh = blockIdx.y;
    const int b = bh >> 3, h = bh & 7;
    __shared__ __align__(16) float Fs[BK16][DH];
    __shared__ __align__(16) float Vs[BK16][DH];
    const float invL = 1.0f / (float)LL;
    const int tid = threadIdx.x;
    const int rowL = tid >> 5;
    const int colL = (tid & 31) * 4;
    const int tr = (tid >> 4) * 8, tc = (tid & 15) * 8;
    float acc[8][8] = {};

    for (int l0 = ch * LC; l0 < ch * LC + LC; l0 += BK16) {
#pragma unroll
        for (int i = 0; i < 2; i++) {
            int l = l0 + rowL + i * 8;
            const float* p = g_q + (size_t)(b * LL + l) * DD + h * DH + colL;
            float4 v = *(const float4*)p;
            float4 f;
            f.x = featf(v.x); f.y = featf(v.y); f.z = featf(v.z); f.w = featf(v.w);
            *(float4*)&Fs[rowL + i * 8][colL] = f;
            float4 vv; vv.x = v.x * invL; vv.y = v.y * invL; vv.z = v.z * invL; vv.w = v.w * invL;
            *(float4*)&Vs[rowL + i * 8][colL] = vv;
        }
        __syncthreads();
#pragma unroll
        for (int kk = 0; kk < BK16; kk++) {
            float4 a0 = *(const float4*)&Fs[kk][tr];
            float4 a1 = *(const float4*)&Fs[kk][tr + 4];
            float4 b0 = *(const float4*)&Vs[kk][tc];
            float4 b1 = *(const float4*)&Vs[kk][tc + 4];
            float ra[8] = {a0.x, a0.y, a0.z, a0.w, a1.x, a1.y, a1.z, a1.w};
            float rb[8] = {b0.x, b0.y, b0.z, b0.w, b1.x, b1.y, b1.z, b1.w};
#pragma unroll
            for (int i = 0; i < 8; i++)
#pragma unroll
                for (int j = 0; j < 8; j++)
                    acc[i][j] = fmaf(ra[i], rb[j], acc[i][j]);
        }
        __syncthreads();
    }
    float* outp = g_kvp + (size_t)(bh * NCH + ch) * (DH * DH);
#pragma unroll
    for (int i = 0; i < 8; i++)
#pragma unroll
        for (int j = 0; j < 8; j += 4) {
            float4 v;
            v.x = acc[i][j]; v.y = acc[i][j + 1]; v.z = acc[i][j + 2]; v.w = acc[i][j + 3];
            *(float4*)(outp + (tr + i) * DH + tc + j) = v;
        }
}

__global__ void kv_reduce_k() {
    int idx = blockIdx.x * 256 + threadIdx.x;
    int bh = idx >> 14;
    int e = idx & 16383;
    float s = 0.f;
#pragma unroll
    for (int c = 0; c < NCH; c++)
        s += g_kvp[(size_t)(bh * NCH + c) * (DH * DH) + e];
    g_kv[idx] = s;
}

__global__ void __launch_bounds__(128) ksum_part_k() {
    const int ch = blockIdx.x, bh = blockIdx.y;
    const int b = bh >> 3, h = bh & 7;
    const int i = threadIdx.x;
    float s = 0.f;
    const float* base = g_q + (size_t)(b * LL + ch * LC) * DD + h * DH + i;
    for (int l = 0; l < LC; l++)
        s += featf(base[(size_t)l * DD]);
    g_ksp[(bh * NCH + ch) * DH + i] = s;
}

__global__ void ksum_reduce_k() {
    int idx = blockIdx.x * 256 + threadIdx.x;
    int bh = idx >> 7;
    int i = idx & 127;
    float s = 0.f;
#pragma unroll
    for (int c = 0; c < NCH; c++)
        s += g_ksp[(bh * NCH + c) * DH + i];
    g_ks[idx] = s;
}

__global__ void __launch_bounds__(256) z_k() {
    __shared__ float sk[BB * HH * DH];
    for (int i = threadIdx.x; i < BB * HH * DH; i += 256) sk[i] = g_ks[i];
    __syncthreads();
    int idx = blockIdx.x * 256 + threadIdx.x;
    int n = idx >> 3;
    int h = idx & 7;
    int b = n >> 13;
    const float* qp = g_q + (size_t)n * DD + h * DH;
    const float* kp = sk + (b * HH + h) * DH;
    float dot = 0.f;
#pragma unroll 4
    for (int i = 0; i < DH; i += 4) {
        float4 v = *(const float4*)(qp + i);
        dot = fmaf(featf(v.x), kp[i + 0], dot);
        dot = fmaf(featf(v.y), kp[i + 1], dot);
        dot = fmaf(featf(v.z), kp[i + 2], dot);
        dot = fmaf(featf(v.w), kp[i + 3], dot);
    }
    g_z[idx] = 1.0f / (dot + ATTN_EPS);
}

// msg -> bf16 hi/lo directly (consumed only by the Wm GEMM)
__global__ void __launch_bounds__(256) msg_k() {
    const int bh = blockIdx.y;
    const int b = bh >> 3, h = bh & 7;
    const int l0 = blockIdx.x * 128;
    __shared__ __align__(16) float As[BK16][128];
    __shared__ __align__(16) float Ks[BK16][DH];
    const int tid = threadIdx.x;
    const int rowA = tid >> 2;
    const int colA = (tid & 3) * 4;
    const int rowB = tid >> 5;
    const int colB = (tid & 31) * 4;
    const int tr = (tid >> 4) * 8, tc = (tid & 15) * 8;
    float acc[8][8] = {};
    const float* kvb = g_kv + (size_t)bh * (DH * DH);

    for (int k0 = 0; k0 < DH; k0 += BK16) {
#pragma unroll
        for (int i = 0; i < 2; i++) {
            int l = l0 + rowA + i * 64;
            float4 v = *(const float4*)(g_q + (size_t)(b * LL + l) * DD + h * DH + k0 + colA);
            As[colA + 0][rowA + i * 64] = featf(v.x);
            As[colA + 1][rowA + i * 64] = featf(v.y);
            As[colA + 2][rowA + i * 64] = featf(v.z);
            As[colA + 3][rowA + i * 64] = featf(v.w);
        }
#pragma unroll
        for (int i = 0; i < 2; i++) {
            float4 v = *(const float4*)(kvb + (size_t)(k0 + rowB + i * 8) * DH + colB);
            *(float4*)(&Ks[rowB + i * 8][colB]) = v;
        }
        __syncthreads();
#pragma unroll
        for (int kk = 0; kk < BK16; kk++) {
            float4 a0 = *(const float4*)&As[kk][tr];
            float4 a1 = *(const float4*)&As[kk][tr + 4];
            float4 b0 = *(const float4*)&Ks[kk][tc];
            float4 b1 = *(const float4*)&Ks[kk][tc + 4];
            float ra[8] = {a0.x, a0.y, a0.z, a0.w, a1.x, a1.y, a1.z, a1.w};
            float rb[8] = {b0.x, b0.y, b0.z, b0.w, b1.x, b1.y, b1.z, b1.w};
#pragma unroll
            for (int i = 0; i < 8; i++)
#pragma unroll
                for (int j = 0; j < 8; j++)
                    acc[i][j] = fmaf(ra[i], rb[j], acc[i][j]);
        }
        __syncthreads();
    }
#pragma unroll
    for (int i = 0; i < 8; i++) {
        int n = b * LL + l0 + tr + i;
        float zs = g_z[n * HH + h] * (float)LL;
        __nv_bfloat16* hp = g_msg_hi + (size_t)n * DD + h * DH + tc;
        __nv_bfloat16* lp = g_msg_lo + (size_t)n * DD + h * DH + tc;
#pragma unroll
        for (int j = 0; j < 8; j += 2) {
            float a = acc[i][j] * zs, bq = acc[i][j + 1] * zs;
            __nv_bfloat16 ha, la, hb, lb;
            splitf(a, ha, la);
            splitf(bq, hb, lb);
            __nv_bfloat162 hh; hh.x = ha; hh.y = hb;
            __nv_bfloat162 ll; ll.x = la; ll.y = lb;
            *(__nv_bfloat162*)(hp + j) = hh;
            *(__nv_bfloat162*)(lp + j) = ll;
        }
    }
}

// ---------------------------------------------------------------------------
// LayerNorm + residual
// ---------------------------------------------------------------------------
__device__ __forceinline__ float warpReduceSum(float v) {
#pragma unroll
    for (int o = 16; o > 0; o >>= 1) v += __shfl_xor_sync(0xffffffffu, v, o);
    return v;
}

__global__ void __launch_bounds__(256) ln_k(const float* __restrict__ t,
                                            const float* __restrict__ base,
                                            const float* __restrict__ gam,
                                            const float* __restrict__ bet,
                                            float* __restrict__ out) {
    const int n = blockIdx.x;
    __shared__ float row[DD];
    __shared__ float rs[8], rs2[8];
    __shared__ float smu, srstd;
    const float* tp = t + (size_t)n * DD;
    float s = 0.f, s2 = 0.f;
    for (int d = threadIdx.x; d < DD; d += 256) {
        float v = tp[d];
        row[d] = v;
        s += v;
        s2 = fmaf(v, v, s2);
    }
    s = warpReduceSum(s);
    s2 = warpReduceSum(s2);
    int lane = threadIdx.x & 31, wid = threadIdx.x >> 5;
    if (lane == 0) { rs[wid] = s; rs2[wid] = s2; }
    __syncthreads();
    if (threadIdx.x < 32) {
        float a = (threadIdx.x < 8) ? rs[threadIdx.x] : 0.f;
        float b2 = (threadIdx.x < 8) ? rs2[threadIdx.x] : 0.f;
        a = warpReduceSum(a);
        b2 = warpReduceSum(b2);
        if (threadIdx.x == 0) {
            float mu = a * (1.0f / DD);
            float var = b2 * (1.0f / DD) - mu * mu;
            smu = mu;
            srstd = rsqrtf(var + LN_EPS);
        }
    }
    __syncthreads();
    float mu = smu, rstd = srstd;
    const float* bp = base + (size_t)n * DD;
    float* op = out + (size_t)n * DD;
    for (int d = threadIdx.x; d < DD; d += 256)
        op[d] = bp[d] + (row[d] - mu) * rstd * gam[d] + bet[d];
}

// ---------------------------------------------------------------------------
extern "C" void kernel_launch(void* const* d_in, const int* in_sizes, int n_in,
                              void* d_out, int out_size) {
    (void)in_sizes; (void)n_in; (void)out_size;
    const float* x  = (const float*)d_in[0];
    const float* Wq = (const float*)d_in[1];
    const float* Wm = (const float*)d_in[2];
    const float* W1 = (const float*)d_in[3];
    const float* W2 = (const float*)d_in[4];
    const float* g1 = (const float*)d_in[5];
    const float* b1 = (const float*)d_in[6];
    const float* g2 = (const float*)d_in[7];
    const float* b2 = (const float*)d_in[8];
    float* out = (float*)d_out;

    float *q, *tmp;
    __nv_bfloat16 *x_hi, *x_lo, *msg_hi, *msg_lo, *tmp_hi, *tmp_lo, *h1_hi, *h1_lo;
    __nv_bfloat16 *wq_hi, *wq_lo, *wm_hi, *wm_lo, *w1_hi, *w1_lo, *w2_hi, *w2_lo;
    cudaGetSymbolAddress((void**)&q,      g_q);
    cudaGetSymbolAddress((void**)&tmp,    g_tmp);
    cudaGetSymbolAddress((void**)&x_hi,   g_x_hi);
    cudaGetSymbolAddress((void**)&x_lo,   g_x_lo);
    cudaGetSymbolAddress((void**)&msg_hi, g_msg_hi);
    cudaGetSymbolAddress((void**)&msg_lo, g_msg_lo);
    cudaGetSymbolAddress((void**)&tmp_hi, g_tmp_hi);
    cudaGetSymbolAddress((void**)&tmp_lo, g_tmp_lo);
    cudaGetSymbolAddress((void**)&h1_hi,  g_h1_hi);
    cudaGetSymbolAddress((void**)&h1_lo,  g_h1_lo);
    cudaGetSymbolAddress((void**)&wq_hi,  g_wq_hi);
    cudaGetSymbolAddress((void**)&wq_lo,  g_wq_lo);
    cudaGetSymbolAddress((void**)&wm_hi,  g_wm_hi);
    cudaGetSymbolAddress((void**)&wm_lo,  g_wm_lo);
    cudaGetSymbolAddress((void**)&w1_hi,  g_w1_hi);
    cudaGetSymbolAddress((void**)&w1_lo,  g_w1_lo);
    cudaGetSymbolAddress((void**)&w2_hi,  g_w2_hi);
    cudaGetSymbolAddress((void**)&w2_lo,  g_w2_lo);

    // 0. Convert inputs: x split; weights transpose+split
    split_k<<<(NROW * DD + 255) / 256, 256>>>(x, x_hi, x_lo, NROW * DD);
    wtrans_k<<<(DD * DD + 255) / 256, 256>>>(Wq, wq_hi, wq_lo, DD, DD);
    wtrans_k<<<(DD * DD + 255) / 256, 256>>>(Wm, wm_hi, wm_lo, DD, DD);
    wtrans_k<<<(DD * DFF + 255) / 256, 256>>>(W1, w1_hi, w1_lo, DD, DFF);
    wtrans_k<<<(DFF * DD + 255) / 256, 256>>>(W2, w2_hi, w2_lo, DFF, DD);

    // 1. q = x @ Wq (fp32 out for attention)
    hgemm_k<0><<<dim3(DD / 128, NROW / 128), 256>>>(
        x_hi, x_lo, wq_hi, wq_lo, q, nullptr, nullptr, DD, DD);
    // 2. attention reductions
    kv_part_k<<<dim3(NCH, BB * HH), 256>>>();
    kv_reduce_k<<<BB * HH * DH * DH / 256, 256>>>();
    ksum_part_k<<<dim3(NCH, BB * HH), 128>>>();
    ksum_reduce_k<<<BB * HH * DH / 256, 256>>>();
    z_k<<<NROW * HH / 256, 256>>>();
    // 3. msg (bf16 hi/lo out)
    msg_k<<<dim3(LL / 128, BB * HH), 256>>>();
    // 4. tmp = msg @ Wm (fp32 + hi/lo)  -- this is the rebinded "msg"
    hgemm_k<1><<<dim3(DD / 128, NROW / 128), 256>>>(
        msg_hi, msg_lo, wm_hi, wm_lo, tmp, tmp_hi, tmp_lo, DD, DD);
    // 5. out = x + LN(tmp)
    ln_k<<<NROW, 256>>>(tmp, x, g1, b1, out);
    // 6. h1 = relu(tmp @ W1) (hi/lo only)
    hgemm_k<2><<<dim3(DFF / 128, NROW / 128), 256>>>(
        tmp_hi, tmp_lo, w1_hi, w1_lo, nullptr, h1_hi, h1_lo, DFF, DD);
    // 7. tmp = h1 @ W2 (fp32)
    hgemm_k<0><<<dim3(DD / 128, NROW / 128), 256>>>(
        h1_hi, h1_lo, w2_hi, w2_lo, tmp, nullptr, nullptr, DD, DFF);
    // 8. out += LN(tmp)
    ln_k<<<NROW, 256>>>(tmp, out, g2, b2, out);
}

// round 6
// speedup vs baseline: 4.1133x; 1.1096x over previous
#include <cuda_runtime.h>
#include <cuda_bf16.h>
#include <math.h>
#include <stdint.h>

// Problem constants
#define BB   2
#define LL   8192
#define DD   1024
#define HH   8
#define DH   128
#define NROW (BB*LL)     // 16384
#define DFF  (2*DD)      // 2048
#define LC   512
#define NCH  (LL/LC)     // 16
#define ATTN_EPS 1e-6f
#define LN_EPS   1e-5f

// ---------------------------------------------------------------------------
// Scratch (device globals: allocation-free per harness rules)
// ---------------------------------------------------------------------------
__device__ float g_q[NROW*DD];                  // x @ Wq (fp32, attention input)
__device__ float g_tmp[NROW*DD];                // msg@Wm fp32 (LN1 input), then mlp out
__device__ float g_kvp[BB*HH*NCH*DH*DH];        // KV partials per L-chunk
__device__ float g_kv[BB*HH*DH*DH];             // KV
__device__ float g_ksp[BB*HH*NCH*DH];           // Ksum partials
__device__ float g_ks[BB*HH*DH];                // Ksum
__device__ float g_z[NROW*HH];                  // 1/(Q.Ksum + eps)

// bf16 hi/lo split operands for tensor-core GEMMs
__device__ __nv_bfloat16 g_x_hi[NROW*DD],   g_x_lo[NROW*DD];
__device__ __nv_bfloat16 g_msg_hi[NROW*DD], g_msg_lo[NROW*DD];
__device__ __nv_bfloat16 g_tmp_hi[NROW*DD], g_tmp_lo[NROW*DD];
__device__ __nv_bfloat16 g_h1_hi[NROW*DFF], g_h1_lo[NROW*DFF];
// transposed+split weights: [N, K] K-major
__device__ __nv_bfloat16 g_wq_hi[DD*DD],  g_wq_lo[DD*DD];
__device__ __nv_bfloat16 g_wm_hi[DD*DD],  g_wm_lo[DD*DD];
__device__ __nv_bfloat16 g_w1_hi[DFF*DD], g_w1_lo[DFF*DD];
__device__ __nv_bfloat16 g_w2_hi[DD*DFF], g_w2_lo[DD*DFF];

// ---------------------------------------------------------------------------
// Helpers
// ---------------------------------------------------------------------------
__device__ __forceinline__ uint32_t smem_u32(const void* p) {
    uint32_t a;
    asm("{ .reg .u64 t; cvta.to.shared.u64 t, %1; cvt.u32.u64 %0, t; }" : "=r"(a) : "l"(p));
    return a;
}

__device__ __forceinline__ void splitf(float v, __nv_bfloat16& h, __nv_bfloat16& l) {
    h = __float2bfloat16(v);
    l = __float2bfloat16(v - __bfloat162float(h));
}

__device__ __forceinline__ float featf(float v) {
    return v > 0.f ? v + 1.f : expf(v);
}

#define LDSM4(r0, r1, r2, r3, addr) \
    asm volatile("ldmatrix.sync.aligned.m8n8.x4.shared.b16 {%0,%1,%2,%3}, [%4];" \
                 : "=r"(r0), "=r"(r1), "=r"(r2), "=r"(r3) : "r"(addr))

#define CP16(dst, src) \
    asm volatile("cp.async.cg.shared.global [%0], [%1], 16;" :: "r"(dst), "l"(src))
#define CP_COMMIT() asm volatile("cp.async.commit_group;" ::: "memory")
#define CP_WAIT1()  asm volatile("cp.async.wait_group 1;" ::: "memory")
#define CP_WAIT0()  asm volatile("cp.async.wait_group 0;" ::: "memory")

__device__ __forceinline__ void mma16816(float* c, const uint32_t* a,
                                         uint32_t b0, uint32_t b1) {
    asm volatile("mma.sync.aligned.m16n8k16.row.col.f32.bf16.bf16.f32 "
                 "{%0,%1,%2,%3}, {%4,%5,%6,%7}, {%8,%9}, {%0,%1,%2,%3};"
                 : "+f"(c[0]), "+f"(c[1]), "+f"(c[2]), "+f"(c[3])
                 : "r"(a[0]), "r"(a[1]), "r"(a[2]), "r"(a[3]), "r"(b0), "r"(b1));
}

// ---------------------------------------------------------------------------
// HMMA GEMM: C[M,N] = (Ahi+Alo)[M,K] @ (Bhi+Blo)^T, B stored [N,K] K-major.
// Block tile 128x128, K-chunk 32, 4 warps (2x2), warp tile 64x64.
// cp.async double-buffered (2 stages). Hi/lo 3-pass: ah*bh + al*bh + ah*bl.
// EPI: 0 = fp32 C; 1 = fp32 C + bf16 hi/lo; 2 = relu then bf16 hi/lo only.
// smem rows padded to 80B (stride 20 words): conflict-free ldmatrix phases.
// ---------------------------------------------------------------------------
#define SROW  80
#define GTILE (128 * SROW)      // one array (128 rows x 32 bf16, padded)
#define GSTG  (4 * GTILE)       // Ah, Al, Bh, Bl
#define GSMEM (2 * GSTG)        // 81920 bytes, two stages

template <int EPI>
__global__ void __launch_bounds__(128, 2)
hgemm_k(const __nv_bfloat16* __restrict__ Ahi, const __nv_bfloat16* __restrict__ Alo,
        const __nv_bfloat16* __restrict__ Bhi, const __nv_bfloat16* __restrict__ Blo,
        float* __restrict__ C, __nv_bfloat16* __restrict__ Chi,
        __nv_bfloat16* __restrict__ Clo, int Nn, int K) {
    extern __shared__ __align__(16) char smem[];
    const uint32_t sb = smem_u32(smem);
    const int tid = threadIdx.x, warp = tid >> 5, lane = tid & 31;
    const int wm = warp >> 1, wn = warp & 1;           // 2 x 2 warp grid
    const int m0 = blockIdx.y * 128, n0 = blockIdx.x * 128;

    float acc[4][8][4] = {};   // [mtile][ntile][reg]

    // ldmatrix per-lane offsets (within one array tile)
    const uint32_t aoff = (uint32_t)(wm * 64 + (lane & 15)) * SROW + ((lane >> 4) << 4);
    const int nloc = (lane & 7) + ((lane >> 4) << 3);
    const uint32_t boff = (uint32_t)(wn * 64 + nloc) * SROW + (((lane >> 3) & 1) << 4);

    // cp.async per-thread: each thread loads 4 rows x 16B per array
    const int lrow = tid >> 2, lseg = tid & 3;

    auto load_stage = [&](int s, int kc) {
        const uint32_t base = sb + (uint32_t)s * GSTG;
#pragma unroll
        for (int i = 0; i < 4; i++) {
            const int r = lrow + i * 32;
            const uint32_t so = (uint32_t)r * SROW + lseg * 16;
            const size_t ga = (size_t)(m0 + r) * K + kc + lseg * 8;
            const size_t gb = (size_t)(n0 + r) * K + kc + lseg * 8;
            CP16(base + 0 * GTILE + so, Ahi + ga);
            CP16(base + 1 * GTILE + so, Alo + ga);
            CP16(base + 2 * GTILE + so, Bhi + gb);
            CP16(base + 3 * GTILE + so, Blo + gb);
        }
    };

    const int nch = K / 32;
    load_stage(0, 0);
    CP_COMMIT();

    for (int c = 0; c < nch; c++) {
        if (c + 1 < nch) {
            load_stage((c + 1) & 1, (c + 1) * 32);
            CP_COMMIT();
            CP_WAIT1();
        } else {
            CP_WAIT0();
        }
        __syncthreads();
        const uint32_t base = sb + (uint32_t)(c & 1) * GSTG;
#pragma unroll
        for (int ks = 0; ks < 2; ks++) {
            const uint32_t kso = (uint32_t)ks * 32;    // 16 bf16 = 32 bytes
            uint32_t ah[4][4], al[4][4], b[4][4];
            // pass 1: ah * bh
#pragma unroll
            for (int mt = 0; mt < 4; mt++)
                LDSM4(ah[mt][0], ah[mt][1], ah[mt][2], ah[mt][3],
                      base + 0 * GTILE + aoff + (uint32_t)mt * 16 * SROW + kso);
#pragma unroll
            for (int p = 0; p < 4; p++)
                LDSM4(b[p][0], b[p][1], b[p][2], b[p][3],
                      base + 2 * GTILE + boff + (uint32_t)p * 16 * SROW + kso);
#pragma unroll
            for (int mt = 0; mt < 4; mt++)
#pragma unroll
                for (int p = 0; p < 4; p++) {
                    mma16816(acc[mt][p * 2 + 0], ah[mt], b[p][0], b[p][1]);
                    mma16816(acc[mt][p * 2 + 1], ah[mt], b[p][2], b[p][3]);
                }
            // pass 2: al * bh
#pragma unroll
            for (int mt = 0; mt < 4; mt++)
                LDSM4(al[mt][0], al[mt][1], al[mt][2], al[mt][3],
                      base + 1 * GTILE + aoff + (uint32_t)mt * 16 * SROW + kso);
#pragma unroll
            for (int mt = 0; mt < 4; mt++)
#pragma unroll
                for (int p = 0; p < 4; p++) {
                    mma16816(acc[mt][p * 2 + 0], al[mt], b[p][0], b[p][1]);
                    mma16816(acc[mt][p * 2 + 1], al[mt], b[p][2], b[p][3]);
                }
            // pass 3: ah * bl (reuse b regs)
#pragma unroll
            for (int p = 0; p < 4; p++)
                LDSM4(b[p][0], b[p][1], b[p][2], b[p][3],
                      base + 3 * GTILE + boff + (uint32_t)p * 16 * SROW + kso);
#pragma unroll
            for (int mt = 0; mt < 4; mt++)
#pragma unroll
                for (int p = 0; p < 4; p++) {
                    mma16816(acc[mt][p * 2 + 0], ah[mt], b[p][0], b[p][1]);
                    mma16816(acc[mt][p * 2 + 1], ah[mt], b[p][2], b[p][3]);
                }
        }
        __syncthreads();
    }

    // Epilogue: m16n8 acc mapping: c0,c1=(gid, t4*2,+1); c2,c3=(gid+8, ...)
    const int gid = lane >> 2, t4 = lane & 3;
#pragma unroll
    for (int mt = 0; mt < 4; mt++) {
#pragma unroll
        for (int nt = 0; nt < 8; nt++) {
            const float* c = acc[mt][nt];
            const int r0 = m0 + wm * 64 + mt * 16 + gid;
            const int cc = n0 + wn * 64 + nt * 8 + t4 * 2;
#pragma unroll
            for (int half = 0; half < 2; half++) {
                const int r = r0 + half * 8;
                float v0 = c[half * 2 + 0], v1 = c[half * 2 + 1];
                if (EPI <= 1) {
                    float2 f; f.x = v0; f.y = v1;
                    *(float2*)(C + (size_t)r * Nn + cc) = f;
                }
                if (EPI >= 1) {
                    if (EPI == 2) { v0 = fmaxf(v0, 0.f); v1 = fmaxf(v1, 0.f); }
                    __nv_bfloat16 h0, l0, h1, l1;
                    splitf(v0, h0, l0);
                    splitf(v1, h1, l1);
                    __nv_bfloat162 hh; hh.x = h0; hh.y = h1;
                    __nv_bfloat162 ll; ll.x = l0; ll.y = l1;
                    *(__nv_bfloat162*)(Chi + (size_t)r * Nn + cc) = hh;
                    *(__nv_bfloat162*)(Clo + (size_t)r * Nn + cc) = ll;
                }
            }
        }
    }
}

// ---------------------------------------------------------------------------
// Conversion kernels
// ---------------------------------------------------------------------------
__global__ void split_k(const float* __restrict__ in, __nv_bfloat16* __restrict__ hi,
                        __nv_bfloat16* __restrict__ lo, int n) {
    int i = blockIdx.x * 256 + threadIdx.x;
    if (i < n) {
        __nv_bfloat16 h, l;
        splitf(in[i], h, l);
        hi[i] = h;
        lo[i] = l;
    }
}

// W [K,N] fp32 -> Wt_hi/lo [N,K] bf16, tiled transpose (coalesced both sides)
__global__ void wtrans_k(const float* __restrict__ W, __nv_bfloat16* __restrict__ Thi,
                         __nv_bfloat16* __restrict__ Tlo, int K, int N) {
    __shared__ float t[32][33];
    const int k0 = blockIdx.y * 32, n0 = blockIdx.x * 32;
    const int tx = threadIdx.x, ty = threadIdx.y;   // 32 x 8
#pragma unroll
    for (int i = 0; i < 4; i++)
        t[ty + i * 8][tx] = W[(size_t)(k0 + ty + i * 8) * N + n0 + tx];
    __syncthreads();
#pragma unroll
    for (int i = 0; i < 4; i++) {
        float v = t[tx][ty + i * 8];
        __nv_bfloat16 h, l;
        splitf(v, h, l);
        const size_t o = (size_t)(n0 + ty + i * 8) * K + k0 + tx;
        Thi[o] = h;
        Tlo[o] = l;
    }
}

// ---------------------------------------------------------------------------
// Attention pieces (fp32 SIMT; small fraction of runtime)
// ---------------------------------------------------------------------------
#define BK16 16

__global__ void __launch_bounds__(256) kv_part_k() {
    const int ch = blockIdx.x, bh = blockIdx.y;
    const int b = bh >> 3, h = bh & 7;
    __shared__ __align__(16) float Fs[BK16][DH];
    __shared__ __align__(16) float Vs[BK16][DH];
    const float invL = 1.0f / (float)LL;
    const int tid = threadIdx.x;
    const int rowL = tid >> 5;
    const int colL = (tid & 31) * 4;
    const int tr = (tid >> 4) * 8, tc = (tid & 15) * 8;
    float acc[8][8] = {};

    for (int l0 = ch * LC; l0 < ch * LC + LC; l0 += BK16) {
#pragma unroll
        for (int i = 0; i < 2; i++) {
            int l = l0 + rowL + i * 8;
            const float* p = g_q + (size_t)(b * LL + l) * DD + h * DH + colL;
            float4 v = *(const float4*)p;
            float4 f;
            f.x = featf(v.x); f.y = featf(v.y); f.z = featf(v.z); f.w = featf(v.w);
            *(float4*)&Fs[rowL + i * 8][colL] = f;
            float4 vv; vv.x = v.x * invL; vv.y = v.y * invL; vv.z = v.z * invL; vv.w = v.w * invL;
            *(float4*)&Vs[rowL + i * 8][colL] = vv;
        }
        __syncthreads();
#pragma unroll
        for (int kk = 0; kk < BK16; kk++) {
            float4 a0 = *(const float4*)&Fs[kk][tr];
            float4 a1 = *(const float4*)&Fs[kk][tr + 4];
            float4 b0 = *(const float4*)&Vs[kk][tc];
            float4 b1 = *(const float4*)&Vs[kk][tc + 4];
            float ra[8] = {a0.x, a0.y, a0.z, a0.w, a1.x, a1.y, a1.z, a1.w};
            float rb[8] = {b0.x, b0.y, b0.z, b0.w, b1.x, b1.y, b1.z, b1.w};
#pragma unroll
            for (int i = 0; i < 8; i++)
#pragma unroll
                for (int j = 0; j < 8; j++)
                    acc[i][j] = fmaf(ra[i], rb[j], acc[i][j]);
        }
        __syncthreads();
    }
    float* outp = g_kvp + (size_t)(bh * NCH + ch) * (DH * DH);
#pragma unroll
    for (int i = 0; i < 8; i++)
#pragma unroll
        for (int j = 0; j < 8; j += 4) {
            float4 v;
            v.x = acc[i][j]; v.y = acc[i][j + 1]; v.z = acc[i][j + 2]; v.w = acc[i][j + 3];
            *(float4*)(outp + (tr + i) * DH + tc + j) = v;
        }
}

__global__ void kv_reduce_k() {
    int idx = blockIdx.x * 256 + threadIdx.x;
    int bh = idx >> 14;
    int e = idx & 16383;
    float s = 0.f;
#pragma unroll
    for (int c = 0; c < NCH; c++)
        s += g_kvp[(size_t)(bh * NCH + c) * (DH * DH) + e];
    g_kv[idx] = s;
}

__global__ void __launch_bounds__(128) ksum_part_k() {
    const int ch = blockIdx.x, bh = blockIdx.y;
    const int b = bh >> 3, h = bh & 7;
    const int i = threadIdx.x;
    float s = 0.f;
    const float* base = g_q + (size_t)(b * LL + ch * LC) * DD + h * DH + i;
    for (int l = 0; l < LC; l++)
        s += featf(base[(size_t)l * DD]);
    g_ksp[(bh * NCH + ch) * DH + i] = s;
}

__global__ void ksum_reduce_k() {
    int idx = blockIdx.x * 256 + threadIdx.x;
    int bh = idx >> 7;
    int i = idx & 127;
    float s = 0.f;
#pragma unroll
    for (int c = 0; c < NCH; c++)
        s += g_ksp[(bh * NCH + c) * DH + i];
    g_ks[idx] = s;
}

__global__ void __launch_bounds__(256) z_k() {
    __shared__ float sk[BB * HH * DH];
    for (int i = threadIdx.x; i < BB * HH * DH; i += 256) sk[i] = g_ks[i];
    __syncthreads();
    int idx = blockIdx.x * 256 + threadIdx.x;
    int n = idx >> 3;
    int h = idx & 7;
    int b = n >> 13;
    const float* qp = g_q + (size_t)n * DD + h * DH;
    const float* kp = sk + (b * HH + h) * DH;
    float dot = 0.f;
#pragma unroll 4
    for (int i = 0; i < DH; i += 4) {
        float4 v = *(const float4*)(qp + i);
        dot = fmaf(featf(v.x), kp[i + 0], dot);
        dot = fmaf(featf(v.y), kp[i + 1], dot);
        dot = fmaf(featf(v.z), kp[i + 2], dot);
        dot = fmaf(featf(v.w), kp[i + 3], dot);
    }
    g_z[idx] = 1.0f / (dot + ATTN_EPS);
}

// msg -> bf16 hi/lo directly (consumed only by the Wm GEMM)
__global__ void __launch_bounds__(256) msg_k() {
    const int bh = blockIdx.y;
    const int b = bh >> 3, h = bh & 7;
    const int l0 = blockIdx.x * 128;
    __shared__ __align__(16) float As[BK16][128];
    __shared__ __align__(16) float Ks[BK16][DH];
    const int tid = threadIdx.x;
    const int rowA = tid >> 2;
    const int colA = (tid & 3) * 4;
    const int rowB = tid >> 5;
    const int colB = (tid & 31) * 4;
    const int tr = (tid >> 4) * 8, tc = (tid & 15) * 8;
    float acc[8][8] = {};
    const float* kvb = g_kv + (size_t)bh * (DH * DH);

    for (int k0 = 0; k0 < DH; k0 += BK16) {
#pragma unroll
        for (int i = 0; i < 2; i++) {
            int l = l0 + rowA + i * 64;
            float4 v = *(const float4*)(g_q + (size_t)(b * LL + l) * DD + h * DH + k0 + colA);
            As[colA + 0][rowA + i * 64] = featf(v.x);
            As[colA + 1][rowA + i * 64] = featf(v.y);
            As[colA + 2][rowA + i * 64] = featf(v.z);
            As[colA + 3][rowA + i * 64] = featf(v.w);
        }
#pragma unroll
        for (int i = 0; i < 2; i++) {
            float4 v = *(const float4*)(kvb + (size_t)(k0 + rowB + i * 8) * DH + colB);
            *(float4*)(&Ks[rowB + i * 8][colB]) = v;
        }
        __syncthreads();
#pragma unroll
        for (int kk = 0; kk < BK16; kk++) {
            float4 a0 = *(const float4*)&As[kk][tr];
            float4 a1 = *(const float4*)&As[kk][tr + 4];
            float4 b0 = *(const float4*)&Ks[kk][tc];
            float4 b1 = *(const float4*)&Ks[kk][tc + 4];
            float ra[8] = {a0.x, a0.y, a0.z, a0.w, a1.x, a1.y, a1.z, a1.w};
            float rb[8] = {b0.x, b0.y, b0.z, b0.w, b1.x, b1.y, b1.z, b1.w};
#pragma unroll
            for (int i = 0; i < 8; i++)
#pragma unroll
                for (int j = 0; j < 8; j++)
                    acc[i][j] = fmaf(ra[i], rb[j], acc[i][j]);
        }
        __syncthreads();
    }
#pragma unroll
    for (int i = 0; i < 8; i++) {
        int n = b * LL + l0 + tr + i;
        float zs = g_z[n * HH + h] * (float)LL;
        __nv_bfloat16* hp = g_msg_hi + (size_t)n * DD + h * DH + tc;
        __nv_bfloat16* lp = g_msg_lo + (size_t)n * DD + h * DH + tc;
#pragma unroll
        for (int j = 0; j < 8; j += 2) {
            float a = acc[i][j] * zs, bq = acc[i][j + 1] * zs;
            __nv_bfloat16 ha, la, hb, lb;
            splitf(a, ha, la);
            splitf(bq, hb, lb);
            __nv_bfloat162 hh; hh.x = ha; hh.y = hb;
            __nv_bfloat162 ll; ll.x = la; ll.y = lb;
            *(__nv_bfloat162*)(hp + j) = hh;
            *(__nv_bfloat162*)(lp + j) = ll;
        }
    }
}

// ---------------------------------------------------------------------------
// LayerNorm + residual
// ---------------------------------------------------------------------------
__device__ __forceinline__ float warpReduceSum(float v) {
#pragma unroll
    for (int o = 16; o > 0; o >>= 1) v += __shfl_xor_sync(0xffffffffu, v, o);
    return v;
}

__global__ void __launch_bounds__(256) ln_k(const float* __restrict__ t,
                                            const float* __restrict__ base,
                                            const float* __restrict__ gam,
                                            const float* __restrict__ bet,
                                            float* __restrict__ out) {
    const int n = blockIdx.x;
    __shared__ float row[DD];
    __shared__ float rs[8], rs2[8];
    __shared__ float smu, srstd;
    const float* tp = t + (size_t)n * DD;
    float s = 0.f, s2 = 0.f;
    for (int d = threadIdx.x; d < DD; d += 256) {
        float v = tp[d];
        row[d] = v;
        s += v;
        s2 = fmaf(v, v, s2);
    }
    s = warpReduceSum(s);
    s2 = warpReduceSum(s2);
    int lane = threadIdx.x & 31, wid = threadIdx.x >> 5;
    if (lane == 0) { rs[wid] = s; rs2[wid] = s2; }
    __syncthreads();
    if (threadIdx.x < 32) {
        float a = (threadIdx.x < 8) ? rs[threadIdx.x] : 0.f;
        float b2 = (threadIdx.x < 8) ? rs2[threadIdx.x] : 0.f;
        a = warpReduceSum(a);
        b2 = warpReduceSum(b2);
        if (threadIdx.x == 0) {
            float mu = a * (1.0f / DD);
            float var = b2 * (1.0f / DD) - mu * mu;
            smu = mu;
            srstd = rsqrtf(var + LN_EPS);
        }
    }
    __syncthreads();
    float mu = smu, rstd = srstd;
    const float* bp = base + (size_t)n * DD;
    float* op = out + (size_t)n * DD;
    for (int d = threadIdx.x; d < DD; d += 256)
        op[d] = bp[d] + (row[d] - mu) * rstd * gam[d] + bet[d];
}

// ---------------------------------------------------------------------------
extern "C" void kernel_launch(void* const* d_in, const int* in_sizes, int n_in,
                              void* d_out, int out_size) {
    (void)in_sizes; (void)n_in; (void)out_size;
    const float* x  = (const float*)d_in[0];
    const float* Wq = (const float*)d_in[1];
    const float* Wm = (const float*)d_in[2];
    const float* W1 = (const float*)d_in[3];
    const float* W2 = (const float*)d_in[4];
    const float* g1 = (const float*)d_in[5];
    const float* b1 = (const float*)d_in[6];
    const float* g2 = (const float*)d_in[7];
    const float* b2 = (const float*)d_in[8];
    float* out = (float*)d_out;

    float *q, *tmp;
    __nv_bfloat16 *x_hi, *x_lo, *msg_hi, *msg_lo, *tmp_hi, *tmp_lo, *h1_hi, *h1_lo;
    __nv_bfloat16 *wq_hi, *wq_lo, *wm_hi, *wm_lo, *w1_hi, *w1_lo, *w2_hi, *w2_lo;
    cudaGetSymbolAddress((void**)&q,      g_q);
    cudaGetSymbolAddress((void**)&tmp,    g_tmp);
    cudaGetSymbolAddress((void**)&x_hi,   g_x_hi);
    cudaGetSymbolAddress((void**)&x_lo,   g_x_lo);
    cudaGetSymbolAddress((void**)&msg_hi, g_msg_hi);
    cudaGetSymbolAddress((void**)&msg_lo, g_msg_lo);
    cudaGetSymbolAddress((void**)&tmp_hi, g_tmp_hi);
    cudaGetSymbolAddress((void**)&tmp_lo, g_tmp_lo);
    cudaGetSymbolAddress((void**)&h1_hi,  g_h1_hi);
    cudaGetSymbolAddress((void**)&h1_lo,  g_h1_lo);
    cudaGetSymbolAddress((void**)&wq_hi,  g_wq_hi);
    cudaGetSymbolAddress((void**)&wq_lo,  g_wq_lo);
    cudaGetSymbolAddress((void**)&wm_hi,  g_wm_hi);
    cudaGetSymbolAddress((void**)&wm_lo,  g_wm_lo);
    cudaGetSymbolAddress((void**)&w1_hi,  g_w1_hi);
    cudaGetSymbolAddress((void**)&w1_lo,  g_w1_lo);
    cudaGetSymbolAddress((void**)&w2_hi,  g_w2_hi);
    cudaGetSymbolAddress((void**)&w2_lo,  g_w2_lo);

    cudaFuncSetAttribute(hgemm_k<0>, cudaFuncAttributeMaxDynamicSharedMemorySize, GSMEM);
    cudaFuncSetAttribute(hgemm_k<1>, cudaFuncAttributeMaxDynamicSharedMemorySize, GSMEM);
    cudaFuncSetAttribute(hgemm_k<2>, cudaFuncAttributeMaxDynamicSharedMemorySize, GSMEM);

    // 0. Convert inputs: x split; weights transpose+split
    split_k<<<(NROW * DD + 255) / 256, 256>>>(x, x_hi, x_lo, NROW * DD);
    wtrans_k<<<dim3(DD / 32, DD / 32), dim3(32, 8)>>>(Wq, wq_hi, wq_lo, DD, DD);
    wtrans_k<<<dim3(DFF / 32, DD / 32), dim3(32, 8)>>>(W1, w1_hi, w1_lo, DD, DFF);
    wtrans_k<<<dim3(DD / 32, DD / 32), dim3(32, 8)>>>(Wm, wm_hi, wm_lo, DD, DD);
    wtrans_k<<<dim3(DD / 32, DFF / 32), dim3(32, 8)>>>(W2, w2_hi, w2_lo, DFF, DD);

    // 1. q = x @ Wq (fp32 out for attention)
    hgemm_k<0><<<dim3(DD / 128, NROW / 128), 128, GSMEM>>>(
        x_hi, x_lo, wq_hi, wq_lo, q, nullptr, nullptr, DD, DD);
    // 2. attention reductions
    kv_part_k<<<dim3(NCH, BB * HH), 256>>>();
    kv_reduce_k<<<BB * HH * DH * DH / 256, 256>>>();
    ksum_part_k<<<dim3(NCH, BB * HH), 128>>>();
    ksum_reduce_k<<<BB * HH * DH / 256, 256>>>();
    z_k<<<NROW * HH / 256, 256>>>();
    // 3. msg (bf16 hi/lo out)
    msg_k<<<dim3(LL / 128, BB * HH), 256>>>();
    // 4. tmp = msg @ Wm (fp32 + hi/lo)  -- this is the rebinded "msg"
    hgemm_k<1><<<dim3(DD / 128, NROW / 128), 128, GSMEM>>>(
        msg_hi, msg_lo, wm_hi, wm_lo, tmp, tmp_hi, tmp_lo, DD, DD);
    // 5. out = x + LN(tmp)
    ln_k<<<NROW, 256>>>(tmp, x, g1, b1, out);
    // 6. h1 = relu(tmp @ W1) (hi/lo only)
    hgemm_k<2><<<dim3(DFF / 128, NROW / 128), 128, GSMEM>>>(
        tmp_hi, tmp_lo, w1_hi, w1_lo, nullptr, h1_hi, h1_lo, DFF, DD);
    // 7. tmp = h1 @ W2 (fp32)
    hgemm_k<0><<<dim3(DD / 128, NROW / 128), 128, GSMEM>>>(
        h1_hi, h1_lo, w2_hi, w2_lo, tmp, nullptr, nullptr, DD, DFF);
    // 8. out += LN(tmp)
    ln_k<<<NROW, 256>>>(tmp, out, g2, b2, out);
}